// round 15
// baseline (speedup 1.0000x reference)
#include <cuda_runtime.h>
#include <cuda_bf16.h>
#include <cmath>
#include <cstdint>

// ---------------- problem constants ----------------
#define HW   4096
#define SB   (64*HW)
#define NB   4
#define T_IN 10
#define STEPS 18
#define STATE_ELEMS (NB*64*HW)
#define YBUF_ELEMS  (NB*32*HW)

// ---------------- device scratch ----------------
__device__ float g_sx0[3*2*STATE_ELEMS];
__device__ float g_sz [3*2*STATE_ELEMS];
__device__ float g_sx1[3*STATE_ELEMS];
__device__ float g_sx2[3*STATE_ELEMS];
__device__ float g_y  [2*3*YBUF_ELEMS];
__device__ float g_pred[STEPS*NB*HW];

// B-fragment weights (bf16 hi/lo packed): [set][cb][tap][nt 0..15][lane 0..31] uint4
__device__ uint4 g_q5a[3*5*25*16*32];
__device__ uint4 g_q3a[3*5*9*16*32];
__device__ uint4 g_q5b[6*6*25*16*32];
__device__ uint4 g_q3b[6*6*9*16*32];
// packed A: [b][cb][px 0..4095][4 x uint4]
__device__ uint4 g_apack[4*6*4096*4];

__device__ __forceinline__ float sigf(float x) { return 1.0f / (1.0f + expf(-x)); }

__device__ __forceinline__ unsigned sptr(const void* p) {
    return (unsigned)__cvta_generic_to_shared(p);
}
__device__ __forceinline__ void cpa16p(unsigned d, const void* s, bool ok) {
    asm volatile("cp.async.cg.shared.global [%0], [%1], 16, %2;"
                 :: "r"(d), "l"(s), "r"(ok ? 16 : 0));
}
#define CP_COMMIT() asm volatile("cp.async.commit_group;")
template<int N> __device__ __forceinline__ void cp_wait() {
    asm volatile("cp.async.wait_group %0;" :: "n"(N));
}

__device__ __forceinline__ unsigned short f2bf(float f) {
    __nv_bfloat16 h = __float2bfloat16_rn(f);
    return *reinterpret_cast<unsigned short*>(&h);
}
__device__ __forceinline__ float bf2f(unsigned short u) {
    __nv_bfloat16 h = *reinterpret_cast<__nv_bfloat16*>(&u);
    return __bfloat162float(h);
}
__device__ __forceinline__ unsigned packbf(float a, float b) {
    return (unsigned)f2bf(a) | ((unsigned)f2bf(b) << 16);
}

#define MMA_BF16(d, a0, a1, a2, a3, b0, b1) \
    asm volatile("mma.sync.aligned.m16n8k16.row.col.f32.bf16.bf16.f32 " \
        "{%0,%1,%2,%3},{%4,%5,%6,%7},{%8,%9},{%0,%1,%2,%3};" \
        : "+f"(d[0]), "+f"(d[1]), "+f"(d[2]), "+f"(d[3]) \
        : "r"(a0), "r"(a1), "r"(a2), "r"(a3), "r"(b0), "r"(b1))

__device__ __forceinline__ void ldsm4(unsigned* r, unsigned addr) {
    asm volatile("ldmatrix.sync.aligned.m8n8.x4.shared.b16 {%0,%1,%2,%3}, [%4];"
        : "=r"(r[0]), "=r"(r[1]), "=r"(r[2]), "=r"(r[3]) : "r"(addr));
}

// ---------------- dummy kernel (profile slot alignment) ----------------
__global__ void warm_kernel(float* p) { if (threadIdx.x == 0) p[0] = 0.f; }

// ---------------- weight -> B-fragment transform + state zeroing ----------------
__device__ __forceinline__ void build_one(const float* __restrict__ w, uint4* __restrict__ dst,
                                          int CIN, int KK, int NCB, long i)
{
    int L  = (int)(i & 31);
    int nt = (int)((i >> 5) & 15);
    long r = i >> 9;
    int tap = (int)(r % KK); r /= KK;
    int cb  = (int)(r % NCB);
    int set = (int)(r / NCB);
    const float* ws = w + (long)set * 128 * CIN * KK;
    int n  = nt * 8 + (L >> 2);
    int gc = (n & 3) * 32 + (n >> 2);
    int k  = L & 3;
    int cins[4] = {cb*16 + 2*k, cb*16 + 2*k + 1, cb*16 + 2*k + 8, cb*16 + 2*k + 9};
    float v[4];
#pragma unroll
    for (int j = 0; j < 4; j++)
        v[j] = (cins[j] < CIN) ? ws[((long)gc * CIN + cins[j]) * KK + tap] : 0.f;
    unsigned short h0 = f2bf(v[0]), h1 = f2bf(v[1]), h2 = f2bf(v[2]), h3 = f2bf(v[3]);
    uint4 o;
    o.x = (unsigned)h0 | ((unsigned)h1 << 16);
    o.y = (unsigned)h2 | ((unsigned)h3 << 16);
    o.z = packbf(v[0] - bf2f(h0), v[1] - bf2f(h1));
    o.w = packbf(v[2] - bf2f(h2), v[3] - bf2f(h3));
    dst[i] = o;
}

#define NQ1 (3L*5*25*512)
#define NQ2 (3L*5*9*512)
#define NQ3 (6L*6*25*512)
#define NQ4 (6L*6*9*512)
#define NZ4 ((long)(6*STATE_ELEMS/4))

__global__ void build_all(const float* __restrict__ wz0, const float* __restrict__ wx0,
                          const float* __restrict__ wz1, const float* __restrict__ wx1,
                          uint4* q5a, uint4* q3a, uint4* q5b, uint4* q3b,
                          float4* __restrict__ zs0, float4* __restrict__ zs1)
{
    long i = (long)blockIdx.x * 256 + threadIdx.x;
    if (i < NQ1) { build_one(wz0, q5a, 65, 25, 5, i); return; }
    i -= NQ1;
    if (i < NQ2) { build_one(wx0, q3a, 65, 9,  5, i); return; }
    i -= NQ2;
    if (i < NQ3) { build_one(wz1, q5b, 96, 25, 6, i); return; }
    i -= NQ3;
    if (i < NQ4) { build_one(wx1, q3b, 96, 9,  6, i); return; }
    i -= NQ4;
    if (i < NZ4) { zs0[i] = make_float4(0.f, 0.f, 0.f, 0.f); return; }
    i -= NZ4;
    if (i < NZ4) { zs1[i] = make_float4(0.f, 0.f, 0.f, 0.f); }
}
#define BUILD_TOTAL (NQ1 + NQ2 + NQ3 + NQ4 + 2*NZ4)

// ---------------- shared pack body ----------------
template<int CINX, int NCB>
__device__ __forceinline__ void pack_body(
    const float* __restrict__ x, int xbs,
    const float* __restrict__ hx, const float* __restrict__ hz,
    uint4* __restrict__ out, int b, int cb, int px)
{
    float v[16];
#pragma unroll
    for (int k = 0; k < 16; k++) {
        int ch = cb * 16 + k;
        if (ch < CINX)            v[k] = x [(long)b * xbs + ch * HW + px];
        else if (ch < CINX + 32)  v[k] = hx[(long)b * SB + (ch - CINX) * HW + px];
        else if (ch < CINX + 64)  v[k] = hz[(long)b * SB + (ch - CINX - 32) * HW + px];
        else                      v[k] = 0.f;
    }
    unsigned hi[8], lo[8];
#pragma unroll
    for (int j = 0; j < 8; j++) {
        unsigned short a = f2bf(v[2*j]), bb = f2bf(v[2*j+1]);
        hi[j] = (unsigned)a | ((unsigned)bb << 16);
        lo[j] = packbf(v[2*j] - bf2f(a), v[2*j+1] - bf2f(bb));
    }
    uint4* o = out + ((long)(b * NCB + cb) * 4096 + px) * 4;
    o[0] = make_uint4(hi[0], hi[1], hi[2], hi[3]);
    o[1] = make_uint4(hi[4], hi[5], hi[6], hi[7]);
    o[2] = make_uint4(lo[0], lo[1], lo[2], lo[3]);
    o[3] = make_uint4(lo[4], lo[5], lo[6], lo[7]);
}

// standalone pack (step-start) + fused final of PREVIOUS step (z == NCB)
template<int CINX, int NCB>
__global__ __launch_bounds__(256) void pack_a(
    const float* __restrict__ x, int xbs,
    const float* __restrict__ hx, const float* __restrict__ hz,
    uint4* __restrict__ out,
    const float* __restrict__ ylast, const float* __restrict__ wl,
    float* __restrict__ predp, float* __restrict__ outp)
{
    const int tid = threadIdx.x;
    const int b = blockIdx.y;
    if (blockIdx.z == NCB) {
        const int i = (blockIdx.y * 16 + blockIdx.x) * 256 + tid;
        const int b2 = i >> 12, px2 = i & 4095;
        float a = 0.f;
#pragma unroll
        for (int oc = 0; oc < 32; ++oc)
            a = fmaf(wl[oc], ylast[(long)b2 * 32 * HW + oc * HW + px2], a);
        predp[i] = a;
        if (outp) outp[(long)b2 * 10 * HW + px2] = a;
        return;
    }
    const int cb = blockIdx.z, px = blockIdx.x * 256 + tid;
    pack_body<CINX, NCB>(x, xbs, hx, hz, out, b, cb, px);
}

// ---------------- fused post kernel: conv_y + pack for NEXT cell ----------------
template<int CINXN, int NCBN>
__global__ __launch_bounds__(256) void post_kernel(
    const float* __restrict__ hx2, const float* __restrict__ hz2,
    const float* __restrict__ wy, const float* __restrict__ by,
    float* __restrict__ y,
    const float* __restrict__ xn, int xbsn,
    const float* __restrict__ hxn, const float* __restrict__ hzn,
    uint4* __restrict__ apack)
{
    const int tid = threadIdx.x;
    const int b = blockIdx.y;
    if (blockIdx.z >= 4) {
        const int cb = blockIdx.z - 4;
        const int px = blockIdx.x * 256 + tid;
        pack_body<CINXN, NCBN>(xn, xbsn, hxn, hzn, apack, b, cb, px);
        return;
    }
    __shared__ float wsm[8 * 64];
    const int og = blockIdx.z;
    for (int i = tid; i < 512; i += 256)
        wsm[i] = wy[(og * 8 + (i >> 6)) * 64 + (i & 63)];
    __syncthreads();

    const int pix = blockIdx.x * 256 + tid;
    float acc[8];
#pragma unroll
    for (int o = 0; o < 8; o++) acc[o] = by[og * 8 + o];
#pragma unroll 8
    for (int ic = 0; ic < 32; ++ic) {
        float v = hx2[(long)b * SB + ic * HW + pix];
#pragma unroll
        for (int o = 0; o < 8; o++) acc[o] = fmaf(v, wsm[o * 64 + ic], acc[o]);
    }
#pragma unroll 8
    for (int ic = 0; ic < 32; ++ic) {
        float v = hz2[(long)b * SB + ic * HW + pix];
#pragma unroll
        for (int o = 0; o < 8; o++) acc[o] = fmaf(v, wsm[o * 64 + 32 + ic], acc[o]);
    }
#pragma unroll
    for (int o = 0; o < 8; o++)
        y[(long)b * 32 * HW + (og * 8 + o) * HW + pix] = acc[o];
}

// ---------------- tensor-core cell kernel (batched LDSM per tap) ----------------
#define TPX   20
#define TROW  (72*TPX)
#define TBUF  (6*TROW)
#define SMEMSZ (3*TBUF*4 + 256*4)

template<int NCB>
__global__ __launch_bounds__(256, 2) void cell_mma(
    const uint4* __restrict__ apack,
    const float* __restrict__ srcx, const float* __restrict__ srcz,
    const uint4* __restrict__ wq5, const uint4* __restrict__ wq3,
    const float* __restrict__ bx, const float* __restrict__ bz,
    float* __restrict__ dstx, float* __restrict__ dstz)
{
    extern __shared__ unsigned smem_u[];
    unsigned* tile = smem_u;
    float* bsm = (float*)(smem_u + 3 * TBUF);

    const int tid = threadIdx.x;
    const int L = tid & 31, wid = tid >> 5;
    const int mw = wid & 1, nw = wid >> 1;
    const int q = L & 3, rr = L >> 2;
    const int hblk = blockIdx.x & 1;
    const int rt = (blockIdx.x >> 1) & 31;
    const int bb = blockIdx.x >> 6;
    const int rbase = 2 * rt - 2;
    const int nt0 = hblk * 8 + nw * 2;

    const unsigned lofs = (unsigned)((L & 15) * (TPX * 4) + (L >> 4) * 16);
    const unsigned tile_sp = sptr(tile);

    if (tid < 128) bsm[tid] = bx[tid];
    else           bsm[tid] = bz[tid - 128];

    auto prefetchA = [&](int cb, int buf) {
        const uint4* src = apack + ((long)(bb * NCB + cb) * 4096) * 4;
        unsigned* tb = tile + buf * TBUF;
#pragma unroll 4
        for (int i = tid; i < 1728; i += 256) {
            int chunk = i & 3, pt = i >> 2;
            int scol = pt % 72, srow = pt / 72;
            int grow = rbase + srow, gcol = scol - 4;
            bool ok = (grow >= 0 && grow < 64 && gcol >= 0 && gcol < 64);
            const void* s = src + (ok ? ((grow * 64 + gcol) * 4 + chunk) : 0);
            cpa16p(sptr(tb + (srow * 72 + scol) * TPX + chunk * 4), s, ok);
        }
        CP_COMMIT();
    };

    float acc5[2][4][4], acc3[2][4][4];
#pragma unroll
    for (int n = 0; n < 2; n++)
#pragma unroll
        for (int m = 0; m < 4; m++)
#pragma unroll
            for (int j = 0; j < 4; j++) { acc5[n][m][j] = 0.f; acc3[n][m][j] = 0.f; }

    prefetchA(0, 0);
    prefetchA(1, 1);
#pragma unroll 1
    for (int cb = 0; cb < NCB; ++cb) {
        if (cb + 1 < NCB) cp_wait<1>(); else cp_wait<0>();
        __syncthreads();
        if (cb + 2 < NCB) prefetchA(cb + 2, (cb + 2) % 3);

        const unsigned tb_sp = tile_sp + (unsigned)((cb % 3) * TBUF * 4);
        const uint4* w5b = wq5 + (long)cb * (25 * 512) + nt0 * 32 + L;
        const uint4* w3b = wq3 + (long)cb * (9 * 512)  + nt0 * 32 + L;

        auto do_row = [&](const int ky, const bool center) {
            const unsigned rowb = tb_sp + (unsigned)(((mw + ky) * 72) * TPX * 4) + lofs;
            const uint4* w5r = w5b + ky * 5 * 512;
            const uint4* w3r = w3b + (ky - 1) * 3 * 512;
#pragma unroll
            for (int kx = 0; kx < 5; ++kx) {
                uint4 B50 = w5r[kx * 512];
                uint4 B51 = w5r[kx * 512 + 32];
                const bool c3 = center && (kx >= 1 && kx <= 3);
                uint4 B30, B31;
                if (c3) { B30 = w3r[(kx - 1) * 512]; B31 = w3r[(kx - 1) * 512 + 32]; }
                const unsigned abase = rowb + (unsigned)((kx + 2) * TPX * 4);
                // batched LDSM: all 4 m-tiles' fragments up front
                unsigned hi[4][4], lo[4][4];
#pragma unroll
                for (int mt = 0; mt < 4; ++mt) {
                    ldsm4(hi[mt], abase + mt * (16 * TPX * 4));
                    ldsm4(lo[mt], abase + mt * (16 * TPX * 4) + 32);
                }
#pragma unroll
                for (int mt = 0; mt < 4; ++mt) {
                    MMA_BF16(acc5[0][mt], hi[mt][0], hi[mt][1], hi[mt][2], hi[mt][3], B50.x, B50.y);
                    MMA_BF16(acc5[1][mt], hi[mt][0], hi[mt][1], hi[mt][2], hi[mt][3], B51.x, B51.y);
                    MMA_BF16(acc5[0][mt], hi[mt][0], hi[mt][1], hi[mt][2], hi[mt][3], B50.z, B50.w);
                    MMA_BF16(acc5[1][mt], hi[mt][0], hi[mt][1], hi[mt][2], hi[mt][3], B51.z, B51.w);
                    MMA_BF16(acc5[0][mt], lo[mt][0], lo[mt][1], lo[mt][2], lo[mt][3], B50.x, B50.y);
                    MMA_BF16(acc5[1][mt], lo[mt][0], lo[mt][1], lo[mt][2], lo[mt][3], B51.x, B51.y);
                }
                if (c3) {
#pragma unroll
                    for (int mt = 0; mt < 4; ++mt) {
                        MMA_BF16(acc3[0][mt], hi[mt][0], hi[mt][1], hi[mt][2], hi[mt][3], B30.x, B30.y);
                        MMA_BF16(acc3[1][mt], hi[mt][0], hi[mt][1], hi[mt][2], hi[mt][3], B31.x, B31.y);
                        MMA_BF16(acc3[0][mt], hi[mt][0], hi[mt][1], hi[mt][2], hi[mt][3], B30.z, B30.w);
                        MMA_BF16(acc3[1][mt], hi[mt][0], hi[mt][1], hi[mt][2], hi[mt][3], B31.z, B31.w);
                        MMA_BF16(acc3[0][mt], lo[mt][0], lo[mt][1], lo[mt][2], lo[mt][3], B30.x, B30.y);
                        MMA_BF16(acc3[1][mt], lo[mt][0], lo[mt][1], lo[mt][2], lo[mt][3], B31.x, B31.y);
                    }
                }
            }
        };
        do_row(0, false);
        do_row(1, true);
        do_row(2, true);
        do_row(3, true);
        do_row(4, false);
    }

    // ---- fused LSTM epilogue ----
    const int rowpix = (2 * rt + mw) * 64;
    auto epi = [&](float (&acc)[2][4][4], const float* bs,
                   const float* __restrict__ csrc, float* __restrict__ dst) {
#pragma unroll
        for (int n = 0; n < 2; n++) {
            int hid = 16 * hblk + 4 * nw + 2 * n + (q >> 1);
            float bi = bs[hid], bf = bs[32 + hid] + 0.01f;
            float bg = bs[64 + hid], bo = bs[96 + hid];
            long baseC = (long)bb * SB + (32 + hid) * HW;
            long baseH = (long)bb * SB + hid * HW;
#pragma unroll
            for (int mt = 0; mt < 4; mt++) {
                float c0 = acc[n][mt][0], c1 = acc[n][mt][1];
                float c2 = acc[n][mt][2], c3 = acc[n][mt][3];
                float o0 = __shfl_xor_sync(0xffffffffu, c0, 1);
                float o1 = __shfl_xor_sync(0xffffffffu, c1, 1);
                float o2 = __shfl_xor_sync(0xffffffffu, c2, 1);
                float o3 = __shfl_xor_sync(0xffffffffu, c3, 1);
                float i0, f0, g0, w0, i1, f1, g1, w1;
                if ((q & 1) == 0) { i0=c0; f0=c1; g0=o0; w0=o1; i1=c2; f1=c3; g1=o2; w1=o3; }
                else              { i0=o0; f0=o1; g0=c0; w0=c1; i1=o2; f1=o3; g1=c2; w1=c3; }
                int pix0 = rowpix + mt * 16 + rr;
                {
                    float cold = csrc[baseC + pix0];
                    float cn = sigf(f0 + bf) * cold + sigf(i0 + bi) * tanhf(g0 + bg);
                    if ((q & 1) == 0) dst[baseH + pix0] = sigf(w0 + bo) * tanhf(cn);
                    else              dst[baseC + pix0] = cn;
                }
                {
                    float cold = csrc[baseC + pix0 + 8];
                    float cn = sigf(f1 + bf) * cold + sigf(i1 + bi) * tanhf(g1 + bg);
                    if ((q & 1) == 0) dst[baseH + pix0 + 8] = sigf(w1 + bo) * tanhf(cn);
                    else              dst[baseC + pix0 + 8] = cn;
                }
            }
        }
    };
    epi(acc3, bsm,       srcx, dstx);
    epi(acc5, bsm + 128, srcz, dstz);
}

// ---------------- final 1x1 conv (last step only) ----------------
__global__ void final_kernel(const float* __restrict__ y, const float* __restrict__ wl,
                             float* __restrict__ pred, float* __restrict__ outp)
{
    const int i = blockIdx.x * 256 + threadIdx.x;
    const int b = i >> 12, pix = i & 4095;
    float a = 0.f;
#pragma unroll
    for (int oc = 0; oc < 32; ++oc) a = fmaf(wl[oc], y[(long)b * 32 * HW + oc * HW + pix], a);
    pred[i] = a;
    if (outp) outp[(long)b * 10 * HW + pix] = a;
}

// ---------------- host orchestration ----------------
extern "C" void kernel_launch(void* const* d_in, const int* in_sizes, int n_in,
                              void* d_out, int out_size)
{
    const float* in     = (const float*)d_in[0];
    const float* w_x0   = (const float*)d_in[1];
    const float* b_x0   = (const float*)d_in[2];
    const float* w_z0   = (const float*)d_in[3];
    const float* b_z0   = (const float*)d_in[4];
    const float* w_y0   = (const float*)d_in[5];
    const float* b_y0   = (const float*)d_in[6];
    const float* w_x1   = (const float*)d_in[7];
    const float* b_x1   = (const float*)d_in[8];
    const float* w_z1   = (const float*)d_in[9];
    const float* b_z1   = (const float*)d_in[10];
    const float* w_y1   = (const float*)d_in[11];
    const float* b_y1   = (const float*)d_in[12];
    const float* w_last = (const float*)d_in[13];
    float* out = (float*)d_out;

    float *sx0, *szp, *sx1, *sx2, *yb, *pred;
    uint4 *q5a, *q3a, *q5b, *q3b, *apack;
    cudaGetSymbolAddress((void**)&sx0,  g_sx0);
    cudaGetSymbolAddress((void**)&szp,  g_sz);
    cudaGetSymbolAddress((void**)&sx1,  g_sx1);
    cudaGetSymbolAddress((void**)&sx2,  g_sx2);
    cudaGetSymbolAddress((void**)&yb,   g_y);
    cudaGetSymbolAddress((void**)&pred, g_pred);
    cudaGetSymbolAddress((void**)&q5a,  g_q5a);
    cudaGetSymbolAddress((void**)&q3a,  g_q3a);
    cudaGetSymbolAddress((void**)&q5b,  g_q5b);
    cudaGetSymbolAddress((void**)&q3b,  g_q3b);
    cudaGetSymbolAddress((void**)&apack, g_apack);

    cudaFuncSetAttribute(cell_mma<5>, cudaFuncAttributeMaxDynamicSharedMemorySize, SMEMSZ);
    cudaFuncSetAttribute(cell_mma<6>, cudaFuncAttributeMaxDynamicSharedMemorySize, SMEMSZ);

    warm_kernel<<<1, 32>>>(pred);   // profile slot alignment

    build_all<<<(int)((BUILD_TOTAL + 255) / 256), 256>>>(w_z0, w_x0, w_z1, w_x1,
                                                         q5a, q3a, q5b, q3b,
                                                         (float4*)sx0, (float4*)szp);

    auto xinput = [&](int step, int l, int s, const float*& xp, int& xbs) {
        if (l == 0) {
            int t = step + s;
            if (t < T_IN) { xp = in + (long)t * HW;              xbs = T_IN * HW; }
            else          { xp = pred + (long)(t - 3) * NB * HW; xbs = HW; }
        } else {
            xp = yb + (((l - 1) & 1) * 3 + s) * (long)YBUF_ELEMS;
            xbs = 32 * HW;
        }
    };
    auto statesrc = [&](int step, int l, int s, float*& sxp, float*& szq) {
        sxp = (s == 0) ? sx0 + (l * 2 + (step & 1)) * (long)STATE_ELEMS
            : (s == 1) ? sx0 + (l * 2 + ((step + 1) & 1)) * (long)STATE_ELEMS
                       : sx1 + l * (long)STATE_ELEMS;
        const int k = step * 3 + s;
        szq = szp + (l * 2 + (k & 1)) * (long)STATE_ELEMS;
    };

    float* ylast = yb + (0 * 3 + 2) * (long)YBUF_ELEMS;

    for (int step = 0; step < STEPS; ++step) {
        {
            const float* xp; int xbs;
            float *sxp, *szq;
            xinput(step, 0, 0, xp, xbs);
            statesrc(step, 0, 0, sxp, szq);
            if (step >= 1) {
                float* predp = pred + (long)(step - 1) * NB * HW;
                float* outp  = (step - 1 >= 8) ? out + (long)(step - 1 - 8) * HW : nullptr;
                pack_a<1, 5><<<dim3(16, 4, 6), 256>>>(xp, xbs, sxp, szq, apack,
                                                      ylast, w_last, predp, outp);
            } else {
                pack_a<1, 5><<<dim3(16, 4, 5), 256>>>(xp, xbs, sxp, szq, apack,
                                                      nullptr, w_last, nullptr, nullptr);
            }
        }
        for (int l = 0; l < 3; ++l) {
            for (int s = 0; s < 3; ++s) {
                float *srcx, *srcz;
                statesrc(step, l, s, srcx, srcz);
                float* dstx = (s == 0) ? sx0 + (l * 2 + ((step + 1) & 1)) * (long)STATE_ELEMS
                            : (s == 1) ? sx1 + l * (long)STATE_ELEMS
                                       : sx2 + l * (long)STATE_ELEMS;
                const int k = step * 3 + s;
                float* dstz = szp + (l * 2 + ((k + 1) & 1)) * (long)STATE_ELEMS;

                const float *bxp, *bzp, *wy, *by;
                const uint4 *wq5, *wq3;
                if (l == 0) {
                    wq5 = q5a + (long)s * 5 * 25 * 512;  wq3 = q3a + (long)s * 5 * 9 * 512;
                    bxp = b_x0 + s * 128;  bzp = b_z0 + s * 128;
                    wy  = w_y0 + (long)s * 32 * 64;  by = b_y0 + s * 32;
                } else {
                    int qq = (l - 1) * 3 + s;
                    wq5 = q5b + (long)qq * 6 * 25 * 512;  wq3 = q3b + (long)qq * 6 * 9 * 512;
                    bxp = b_x1 + qq * 128;  bzp = b_z1 + qq * 128;
                    wy  = w_y1 + (long)qq * 32 * 64;  by = b_y1 + qq * 32;
                }

                if (l == 0)
                    cell_mma<5><<<256, 256, SMEMSZ>>>(apack, srcx, srcz, wq5, wq3,
                                                      bxp, bzp, dstx, dstz);
                else
                    cell_mma<6><<<256, 256, SMEMSZ>>>(apack, srcx, srcz, wq5, wq3,
                                                      bxp, bzp, dstx, dstz);

                float* ydst = yb + ((l & 1) * 3 + s) * (long)YBUF_ELEMS;

                const bool last_cell = (l == 2 && s == 2);
                if (!last_cell) {
                    int ln = (s < 2) ? l : l + 1;
                    int sn = (s < 2) ? s + 1 : 0;
                    const float* xn; int xbsn;
                    float *sxn, *szn;
                    xinput(step, ln, sn, xn, xbsn);
                    if (sn == 0) statesrc(step, ln, sn, sxn, szn);
                    else { sxn = dstx; szn = dstz; }
                    if (ln == 0)
                        post_kernel<1, 5><<<dim3(16, 4, 9), 256>>>(
                            dstx, dstz, wy, by, ydst, xn, xbsn, sxn, szn, apack);
                    else
                        post_kernel<32, 6><<<dim3(16, 4, 10), 256>>>(
                            dstx, dstz, wy, by, ydst, xn, xbsn, sxn, szn, apack);
                } else {
                    post_kernel<32, 6><<<dim3(16, 4, 4), 256>>>(
                        dstx, dstz, wy, by, ydst, nullptr, 0, dstx, dstz, apack);
                }
            }
        }
    }
    final_kernel<<<64, 256>>>(ylast, w_last, pred + (long)(STEPS - 1) * NB * HW,
                              out + (long)(STEPS - 1 - 8) * HW);
}

// round 16
// speedup vs baseline: 1.0044x; 1.0044x over previous
#include <cuda_runtime.h>
#include <cuda_bf16.h>
#include <cmath>
#include <cstdint>

// ---------------- problem constants ----------------
#define HW   4096
#define SB   (64*HW)
#define NB   4
#define T_IN 10
#define STEPS 18
#define STATE_ELEMS (NB*64*HW)
#define YBUF_ELEMS  (NB*32*HW)

// ---------------- device scratch ----------------
__device__ float g_sx0[3*2*STATE_ELEMS];
__device__ float g_sz [3*2*STATE_ELEMS];
__device__ float g_sx1[3*STATE_ELEMS];
__device__ float g_sx2[3*STATE_ELEMS];
__device__ float g_y  [2*3*YBUF_ELEMS];
__device__ float g_pred[STEPS*NB*HW];

// B-fragment weights (bf16 hi/lo packed): [set][cb][tap][nt 0..15][lane 0..31] uint4
__device__ uint4 g_q5a[3*5*25*16*32];
__device__ uint4 g_q3a[3*5*9*16*32];
__device__ uint4 g_q5b[6*6*25*16*32];
__device__ uint4 g_q3b[6*6*9*16*32];
// packed A: [b][cb][px 0..4095][4 x uint4]
__device__ uint4 g_apack[4*6*4096*4];

__device__ __forceinline__ float sigf(float x) { return 1.0f / (1.0f + expf(-x)); }

__device__ __forceinline__ unsigned sptr(const void* p) {
    return (unsigned)__cvta_generic_to_shared(p);
}
__device__ __forceinline__ void cpa16p(unsigned d, const void* s, bool ok) {
    asm volatile("cp.async.cg.shared.global [%0], [%1], 16, %2;"
                 :: "r"(d), "l"(s), "r"(ok ? 16 : 0));
}
#define CP_COMMIT() asm volatile("cp.async.commit_group;")
template<int N> __device__ __forceinline__ void cp_wait() {
    asm volatile("cp.async.wait_group %0;" :: "n"(N));
}

__device__ __forceinline__ unsigned short f2bf(float f) {
    __nv_bfloat16 h = __float2bfloat16_rn(f);
    return *reinterpret_cast<unsigned short*>(&h);
}
__device__ __forceinline__ float bf2f(unsigned short u) {
    __nv_bfloat16 h = *reinterpret_cast<__nv_bfloat16*>(&u);
    return __bfloat162float(h);
}
__device__ __forceinline__ unsigned packbf(float a, float b) {
    return (unsigned)f2bf(a) | ((unsigned)f2bf(b) << 16);
}

#define MMA_BF16(d, a0, a1, a2, a3, b0, b1) \
    asm volatile("mma.sync.aligned.m16n8k16.row.col.f32.bf16.bf16.f32 " \
        "{%0,%1,%2,%3},{%4,%5,%6,%7},{%8,%9},{%0,%1,%2,%3};" \
        : "+f"(d[0]), "+f"(d[1]), "+f"(d[2]), "+f"(d[3]) \
        : "r"(a0), "r"(a1), "r"(a2), "r"(a3), "r"(b0), "r"(b1))

__device__ __forceinline__ void ldsm4(unsigned* r, unsigned addr) {
    asm volatile("ldmatrix.sync.aligned.m8n8.x4.shared.b16 {%0,%1,%2,%3}, [%4];"
        : "=r"(r[0]), "=r"(r[1]), "=r"(r[2]), "=r"(r[3]) : "r"(addr));
}

// ---------------- dummy kernel (profile slot alignment) ----------------
__global__ void warm_kernel(float* p) { if (threadIdx.x == 0) p[0] = 0.f; }

// ---------------- weight -> B-fragment transform + state zeroing ----------------
__device__ __forceinline__ void build_one(const float* __restrict__ w, uint4* __restrict__ dst,
                                          int CIN, int KK, int NCB, long i)
{
    int L  = (int)(i & 31);
    int nt = (int)((i >> 5) & 15);
    long r = i >> 9;
    int tap = (int)(r % KK); r /= KK;
    int cb  = (int)(r % NCB);
    int set = (int)(r / NCB);
    const float* ws = w + (long)set * 128 * CIN * KK;
    int n  = nt * 8 + (L >> 2);
    int gc = (n & 3) * 32 + (n >> 2);
    int k  = L & 3;
    int cins[4] = {cb*16 + 2*k, cb*16 + 2*k + 1, cb*16 + 2*k + 8, cb*16 + 2*k + 9};
    float v[4];
#pragma unroll
    for (int j = 0; j < 4; j++)
        v[j] = (cins[j] < CIN) ? ws[((long)gc * CIN + cins[j]) * KK + tap] : 0.f;
    unsigned short h0 = f2bf(v[0]), h1 = f2bf(v[1]), h2 = f2bf(v[2]), h3 = f2bf(v[3]);
    uint4 o;
    o.x = (unsigned)h0 | ((unsigned)h1 << 16);
    o.y = (unsigned)h2 | ((unsigned)h3 << 16);
    o.z = packbf(v[0] - bf2f(h0), v[1] - bf2f(h1));
    o.w = packbf(v[2] - bf2f(h2), v[3] - bf2f(h3));
    dst[i] = o;
}

#define NQ1 (3L*5*25*512)
#define NQ2 (3L*5*9*512)
#define NQ3 (6L*6*25*512)
#define NQ4 (6L*6*9*512)
#define NZ4 ((long)(6*STATE_ELEMS/4))

__global__ void build_all(const float* __restrict__ wz0, const float* __restrict__ wx0,
                          const float* __restrict__ wz1, const float* __restrict__ wx1,
                          uint4* q5a, uint4* q3a, uint4* q5b, uint4* q3b,
                          float4* __restrict__ zs0, float4* __restrict__ zs1)
{
    long i = (long)blockIdx.x * 256 + threadIdx.x;
    if (i < NQ1) { build_one(wz0, q5a, 65, 25, 5, i); return; }
    i -= NQ1;
    if (i < NQ2) { build_one(wx0, q3a, 65, 9,  5, i); return; }
    i -= NQ2;
    if (i < NQ3) { build_one(wz1, q5b, 96, 25, 6, i); return; }
    i -= NQ3;
    if (i < NQ4) { build_one(wx1, q3b, 96, 9,  6, i); return; }
    i -= NQ4;
    if (i < NZ4) { zs0[i] = make_float4(0.f, 0.f, 0.f, 0.f); return; }
    i -= NZ4;
    if (i < NZ4) { zs1[i] = make_float4(0.f, 0.f, 0.f, 0.f); }
}
#define BUILD_TOTAL (NQ1 + NQ2 + NQ3 + NQ4 + 2*NZ4)

// ---------------- shared pack body ----------------
template<int CINX, int NCB>
__device__ __forceinline__ void pack_body(
    const float* __restrict__ x, int xbs,
    const float* __restrict__ hx, const float* __restrict__ hz,
    uint4* __restrict__ out, int b, int cb, int px)
{
    float v[16];
#pragma unroll
    for (int k = 0; k < 16; k++) {
        int ch = cb * 16 + k;
        if (ch < CINX)            v[k] = x [(long)b * xbs + ch * HW + px];
        else if (ch < CINX + 32)  v[k] = hx[(long)b * SB + (ch - CINX) * HW + px];
        else if (ch < CINX + 64)  v[k] = hz[(long)b * SB + (ch - CINX - 32) * HW + px];
        else                      v[k] = 0.f;
    }
    unsigned hi[8], lo[8];
#pragma unroll
    for (int j = 0; j < 8; j++) {
        unsigned short a = f2bf(v[2*j]), bb = f2bf(v[2*j+1]);
        hi[j] = (unsigned)a | ((unsigned)bb << 16);
        lo[j] = packbf(v[2*j] - bf2f(a), v[2*j+1] - bf2f(bb));
    }
    uint4* o = out + ((long)(b * NCB + cb) * 4096 + px) * 4;
    o[0] = make_uint4(hi[0], hi[1], hi[2], hi[3]);
    o[1] = make_uint4(hi[4], hi[5], hi[6], hi[7]);
    o[2] = make_uint4(lo[0], lo[1], lo[2], lo[3]);
    o[3] = make_uint4(lo[4], lo[5], lo[6], lo[7]);
}

// standalone pack (step-start) + fused final of PREVIOUS step (z == NCB)
template<int CINX, int NCB>
__global__ __launch_bounds__(256) void pack_a(
    const float* __restrict__ x, int xbs,
    const float* __restrict__ hx, const float* __restrict__ hz,
    uint4* __restrict__ out,
    const float* __restrict__ ylast, const float* __restrict__ wl,
    float* __restrict__ predp, float* __restrict__ outp)
{
    const int tid = threadIdx.x;
    const int b = blockIdx.y;
    if (blockIdx.z == NCB) {
        const int i = (blockIdx.y * 16 + blockIdx.x) * 256 + tid;
        const int b2 = i >> 12, px2 = i & 4095;
        float a = 0.f;
#pragma unroll
        for (int oc = 0; oc < 32; ++oc)
            a = fmaf(wl[oc], ylast[(long)b2 * 32 * HW + oc * HW + px2], a);
        predp[i] = a;
        if (outp) outp[(long)b2 * 10 * HW + px2] = a;
        return;
    }
    const int cb = blockIdx.z, px = blockIdx.x * 256 + tid;
    pack_body<CINX, NCB>(x, xbs, hx, hz, out, b, cb, px);
}

// ---------------- fused post kernel: conv_y + pack for NEXT cell ----------------
template<int CINXN, int NCBN>
__global__ __launch_bounds__(256) void post_kernel(
    const float* __restrict__ hx2, const float* __restrict__ hz2,
    const float* __restrict__ wy, const float* __restrict__ by,
    float* __restrict__ y,
    const float* __restrict__ xn, int xbsn,
    const float* __restrict__ hxn, const float* __restrict__ hzn,
    uint4* __restrict__ apack)
{
    const int tid = threadIdx.x;
    const int b = blockIdx.y;
    if (blockIdx.z >= 4) {
        const int cb = blockIdx.z - 4;
        const int px = blockIdx.x * 256 + tid;
        pack_body<CINXN, NCBN>(xn, xbsn, hxn, hzn, apack, b, cb, px);
        return;
    }
    __shared__ float wsm[8 * 64];
    const int og = blockIdx.z;
    for (int i = tid; i < 512; i += 256)
        wsm[i] = wy[(og * 8 + (i >> 6)) * 64 + (i & 63)];
    __syncthreads();

    const int pix = blockIdx.x * 256 + tid;
    float acc[8];
#pragma unroll
    for (int o = 0; o < 8; o++) acc[o] = by[og * 8 + o];
#pragma unroll 8
    for (int ic = 0; ic < 32; ++ic) {
        float v = hx2[(long)b * SB + ic * HW + pix];
#pragma unroll
        for (int o = 0; o < 8; o++) acc[o] = fmaf(v, wsm[o * 64 + ic], acc[o]);
    }
#pragma unroll 8
    for (int ic = 0; ic < 32; ++ic) {
        float v = hz2[(long)b * SB + ic * HW + pix];
#pragma unroll
        for (int o = 0; o < 8; o++) acc[o] = fmaf(v, wsm[o * 64 + 32 + ic], acc[o]);
    }
#pragma unroll
    for (int o = 0; o < 8; o++)
        y[(long)b * 32 * HW + (og * 8 + o) * HW + pix] = acc[o];
}

// ---------------- tensor-core cell kernel (pass-reordered MMAs) ----------------
#define TPX   20
#define TROW  (72*TPX)
#define TBUF  (6*TROW)
#define SMEMSZ (3*TBUF*4 + 256*4)

template<int NCB>
__global__ __launch_bounds__(256, 2) void cell_mma(
    const uint4* __restrict__ apack,
    const float* __restrict__ srcx, const float* __restrict__ srcz,
    const uint4* __restrict__ wq5, const uint4* __restrict__ wq3,
    const float* __restrict__ bx, const float* __restrict__ bz,
    float* __restrict__ dstx, float* __restrict__ dstz)
{
    extern __shared__ unsigned smem_u[];
    unsigned* tile = smem_u;
    float* bsm = (float*)(smem_u + 3 * TBUF);

    const int tid = threadIdx.x;
    const int L = tid & 31, wid = tid >> 5;
    const int mw = wid & 1, nw = wid >> 1;
    const int q = L & 3, rr = L >> 2;
    const int hblk = blockIdx.x & 1;
    const int rt = (blockIdx.x >> 1) & 31;
    const int bb = blockIdx.x >> 6;
    const int rbase = 2 * rt - 2;
    const int nt0 = hblk * 8 + nw * 2;

    const unsigned lofs = (unsigned)((L & 15) * (TPX * 4) + (L >> 4) * 16);
    const unsigned tile_sp = sptr(tile);

    if (tid < 128) bsm[tid] = bx[tid];
    else           bsm[tid] = bz[tid - 128];

    auto prefetchA = [&](int cb, int buf) {
        const uint4* src = apack + ((long)(bb * NCB + cb) * 4096) * 4;
        unsigned* tb = tile + buf * TBUF;
#pragma unroll 4
        for (int i = tid; i < 1728; i += 256) {
            int chunk = i & 3, pt = i >> 2;
            int scol = pt % 72, srow = pt / 72;
            int grow = rbase + srow, gcol = scol - 4;
            bool ok = (grow >= 0 && grow < 64 && gcol >= 0 && gcol < 64);
            const void* s = src + (ok ? ((grow * 64 + gcol) * 4 + chunk) : 0);
            cpa16p(sptr(tb + (srow * 72 + scol) * TPX + chunk * 4), s, ok);
        }
        CP_COMMIT();
    };

    float acc5[2][4][4], acc3[2][4][4];
#pragma unroll
    for (int n = 0; n < 2; n++)
#pragma unroll
        for (int m = 0; m < 4; m++)
#pragma unroll
            for (int j = 0; j < 4; j++) { acc5[n][m][j] = 0.f; acc3[n][m][j] = 0.f; }

    prefetchA(0, 0);
    prefetchA(1, 1);
#pragma unroll 1
    for (int cb = 0; cb < NCB; ++cb) {
        if (cb + 1 < NCB) cp_wait<1>(); else cp_wait<0>();
        __syncthreads();
        if (cb + 2 < NCB) prefetchA(cb + 2, (cb + 2) % 3);

        const unsigned tb_sp = tile_sp + (unsigned)((cb % 3) * TBUF * 4);
        const uint4* w5b = wq5 + (long)cb * (25 * 512) + nt0 * 32 + L;
        const uint4* w3b = wq3 + (long)cb * (9 * 512)  + nt0 * 32 + L;

        auto do_row = [&](const int ky, const bool center) {
            const unsigned rowb = tb_sp + (unsigned)(((mw + ky) * 72) * TPX * 4) + lofs;
            const uint4* w5r = w5b + ky * 5 * 512;
            const uint4* w3r = w3b + (ky - 1) * 3 * 512;
#pragma unroll
            for (int kx = 0; kx < 5; ++kx) {
                uint4 B50 = w5r[kx * 512];
                uint4 B51 = w5r[kx * 512 + 32];
                const bool c3 = center && (kx >= 1 && kx <= 3);
                uint4 B30, B31;
                if (c3) { B30 = w3r[(kx - 1) * 512]; B31 = w3r[(kx - 1) * 512 + 32]; }
                const unsigned abase = rowb + (unsigned)((kx + 2) * TPX * 4);
                // batched LDSM: all 4 m-tiles' fragments up front
                unsigned hi[4][4], lo[4][4];
#pragma unroll
                for (int mt = 0; mt < 4; ++mt) {
                    ldsm4(hi[mt], abase + mt * (16 * TPX * 4));
                    ldsm4(lo[mt], abase + mt * (16 * TPX * 4) + 32);
                }
                // pass-reordered MMAs: same-acc reuse distance = 8 MMAs
#pragma unroll
                for (int mt = 0; mt < 4; ++mt) {
                    MMA_BF16(acc5[0][mt], hi[mt][0], hi[mt][1], hi[mt][2], hi[mt][3], B50.x, B50.y);
                    MMA_BF16(acc5[1][mt], hi[mt][0], hi[mt][1], hi[mt][2], hi[mt][3], B51.x, B51.y);
                }
#pragma unroll
                for (int mt = 0; mt < 4; ++mt) {
                    MMA_BF16(acc5[0][mt], hi[mt][0], hi[mt][1], hi[mt][2], hi[mt][3], B50.z, B50.w);
                    MMA_BF16(acc5[1][mt], hi[mt][0], hi[mt][1], hi[mt][2], hi[mt][3], B51.z, B51.w);
                }
#pragma unroll
                for (int mt = 0; mt < 4; ++mt) {
                    MMA_BF16(acc5[0][mt], lo[mt][0], lo[mt][1], lo[mt][2], lo[mt][3], B50.x, B50.y);
                    MMA_BF16(acc5[1][mt], lo[mt][0], lo[mt][1], lo[mt][2], lo[mt][3], B51.x, B51.y);
                }
                if (c3) {
#pragma unroll
                    for (int mt = 0; mt < 4; ++mt) {
                        MMA_BF16(acc3[0][mt], hi[mt][0], hi[mt][1], hi[mt][2], hi[mt][3], B30.x, B30.y);
                        MMA_BF16(acc3[1][mt], hi[mt][0], hi[mt][1], hi[mt][2], hi[mt][3], B31.x, B31.y);
                    }
#pragma unroll
                    for (int mt = 0; mt < 4; ++mt) {
                        MMA_BF16(acc3[0][mt], hi[mt][0], hi[mt][1], hi[mt][2], hi[mt][3], B30.z, B30.w);
                        MMA_BF16(acc3[1][mt], hi[mt][0], hi[mt][1], hi[mt][2], hi[mt][3], B31.z, B31.w);
                    }
#pragma unroll
                    for (int mt = 0; mt < 4; ++mt) {
                        MMA_BF16(acc3[0][mt], lo[mt][0], lo[mt][1], lo[mt][2], lo[mt][3], B30.x, B30.y);
                        MMA_BF16(acc3[1][mt], lo[mt][0], lo[mt][1], lo[mt][2], lo[mt][3], B31.x, B31.y);
                    }
                }
            }
        };
        do_row(0, false);
        do_row(1, true);
        do_row(2, true);
        do_row(3, true);
        do_row(4, false);
    }

    // ---- fused LSTM epilogue ----
    const int rowpix = (2 * rt + mw) * 64;
    auto epi = [&](float (&acc)[2][4][4], const float* bs,
                   const float* __restrict__ csrc, float* __restrict__ dst) {
#pragma unroll
        for (int n = 0; n < 2; n++) {
            int hid = 16 * hblk + 4 * nw + 2 * n + (q >> 1);
            float bi = bs[hid], bf = bs[32 + hid] + 0.01f;
            float bg = bs[64 + hid], bo = bs[96 + hid];
            long baseC = (long)bb * SB + (32 + hid) * HW;
            long baseH = (long)bb * SB + hid * HW;
#pragma unroll
            for (int mt = 0; mt < 4; mt++) {
                float c0 = acc[n][mt][0], c1 = acc[n][mt][1];
                float c2 = acc[n][mt][2], c3 = acc[n][mt][3];
                float o0 = __shfl_xor_sync(0xffffffffu, c0, 1);
                float o1 = __shfl_xor_sync(0xffffffffu, c1, 1);
                float o2 = __shfl_xor_sync(0xffffffffu, c2, 1);
                float o3 = __shfl_xor_sync(0xffffffffu, c3, 1);
                float i0, f0, g0, w0, i1, f1, g1, w1;
                if ((q & 1) == 0) { i0=c0; f0=c1; g0=o0; w0=o1; i1=c2; f1=c3; g1=o2; w1=o3; }
                else              { i0=o0; f0=o1; g0=c0; w0=c1; i1=o2; f1=o3; g1=c2; w1=c3; }
                int pix0 = rowpix + mt * 16 + rr;
                {
                    float cold = csrc[baseC + pix0];
                    float cn = sigf(f0 + bf) * cold + sigf(i0 + bi) * tanhf(g0 + bg);
                    if ((q & 1) == 0) dst[baseH + pix0] = sigf(w0 + bo) * tanhf(cn);
                    else              dst[baseC + pix0] = cn;
                }
                {
                    float cold = csrc[baseC + pix0 + 8];
                    float cn = sigf(f1 + bf) * cold + sigf(i1 + bi) * tanhf(g1 + bg);
                    if ((q & 1) == 0) dst[baseH + pix0 + 8] = sigf(w1 + bo) * tanhf(cn);
                    else              dst[baseC + pix0 + 8] = cn;
                }
            }
        }
    };
    epi(acc3, bsm,       srcx, dstx);
    epi(acc5, bsm + 128, srcz, dstz);
}

// ---------------- final 1x1 conv (last step only) ----------------
__global__ void final_kernel(const float* __restrict__ y, const float* __restrict__ wl,
                             float* __restrict__ pred, float* __restrict__ outp)
{
    const int i = blockIdx.x * 256 + threadIdx.x;
    const int b = i >> 12, pix = i & 4095;
    float a = 0.f;
#pragma unroll
    for (int oc = 0; oc < 32; ++oc) a = fmaf(wl[oc], y[(long)b * 32 * HW + oc * HW + pix], a);
    pred[i] = a;
    if (outp) outp[(long)b * 10 * HW + pix] = a;
}

// ---------------- host orchestration ----------------
extern "C" void kernel_launch(void* const* d_in, const int* in_sizes, int n_in,
                              void* d_out, int out_size)
{
    const float* in     = (const float*)d_in[0];
    const float* w_x0   = (const float*)d_in[1];
    const float* b_x0   = (const float*)d_in[2];
    const float* w_z0   = (const float*)d_in[3];
    const float* b_z0   = (const float*)d_in[4];
    const float* w_y0   = (const float*)d_in[5];
    const float* b_y0   = (const float*)d_in[6];
    const float* w_x1   = (const float*)d_in[7];
    const float* b_x1   = (const float*)d_in[8];
    const float* w_z1   = (const float*)d_in[9];
    const float* b_z1   = (const float*)d_in[10];
    const float* w_y1   = (const float*)d_in[11];
    const float* b_y1   = (const float*)d_in[12];
    const float* w_last = (const float*)d_in[13];
    float* out = (float*)d_out;

    float *sx0, *szp, *sx1, *sx2, *yb, *pred;
    uint4 *q5a, *q3a, *q5b, *q3b, *apack;
    cudaGetSymbolAddress((void**)&sx0,  g_sx0);
    cudaGetSymbolAddress((void**)&szp,  g_sz);
    cudaGetSymbolAddress((void**)&sx1,  g_sx1);
    cudaGetSymbolAddress((void**)&sx2,  g_sx2);
    cudaGetSymbolAddress((void**)&yb,   g_y);
    cudaGetSymbolAddress((void**)&pred, g_pred);
    cudaGetSymbolAddress((void**)&q5a,  g_q5a);
    cudaGetSymbolAddress((void**)&q3a,  g_q3a);
    cudaGetSymbolAddress((void**)&q5b,  g_q5b);
    cudaGetSymbolAddress((void**)&q3b,  g_q3b);
    cudaGetSymbolAddress((void**)&apack, g_apack);

    cudaFuncSetAttribute(cell_mma<5>, cudaFuncAttributeMaxDynamicSharedMemorySize, SMEMSZ);
    cudaFuncSetAttribute(cell_mma<6>, cudaFuncAttributeMaxDynamicSharedMemorySize, SMEMSZ);

    warm_kernel<<<1, 32>>>(pred);   // profile slot alignment

    build_all<<<(int)((BUILD_TOTAL + 255) / 256), 256>>>(w_z0, w_x0, w_z1, w_x1,
                                                         q5a, q3a, q5b, q3b,
                                                         (float4*)sx0, (float4*)szp);

    auto xinput = [&](int step, int l, int s, const float*& xp, int& xbs) {
        if (l == 0) {
            int t = step + s;
            if (t < T_IN) { xp = in + (long)t * HW;              xbs = T_IN * HW; }
            else          { xp = pred + (long)(t - 3) * NB * HW; xbs = HW; }
        } else {
            xp = yb + (((l - 1) & 1) * 3 + s) * (long)YBUF_ELEMS;
            xbs = 32 * HW;
        }
    };
    auto statesrc = [&](int step, int l, int s, float*& sxp, float*& szq) {
        sxp = (s == 0) ? sx0 + (l * 2 + (step & 1)) * (long)STATE_ELEMS
            : (s == 1) ? sx0 + (l * 2 + ((step + 1) & 1)) * (long)STATE_ELEMS
                       : sx1 + l * (long)STATE_ELEMS;
        const int k = step * 3 + s;
        szq = szp + (l * 2 + (k & 1)) * (long)STATE_ELEMS;
    };

    float* ylast = yb + (0 * 3 + 2) * (long)YBUF_ELEMS;

    for (int step = 0; step < STEPS; ++step) {
        {
            const float* xp; int xbs;
            float *sxp, *szq;
            xinput(step, 0, 0, xp, xbs);
            statesrc(step, 0, 0, sxp, szq);
            if (step >= 1) {
                float* predp = pred + (long)(step - 1) * NB * HW;
                float* outp  = (step - 1 >= 8) ? out + (long)(step - 1 - 8) * HW : nullptr;
                pack_a<1, 5><<<dim3(16, 4, 6), 256>>>(xp, xbs, sxp, szq, apack,
                                                      ylast, w_last, predp, outp);
            } else {
                pack_a<1, 5><<<dim3(16, 4, 5), 256>>>(xp, xbs, sxp, szq, apack,
                                                      nullptr, w_last, nullptr, nullptr);
            }
        }
        for (int l = 0; l < 3; ++l) {
            for (int s = 0; s < 3; ++s) {
                float *srcx, *srcz;
                statesrc(step, l, s, srcx, srcz);
                float* dstx = (s == 0) ? sx0 + (l * 2 + ((step + 1) & 1)) * (long)STATE_ELEMS
                            : (s == 1) ? sx1 + l * (long)STATE_ELEMS
                                       : sx2 + l * (long)STATE_ELEMS;
                const int k = step * 3 + s;
                float* dstz = szp + (l * 2 + ((k + 1) & 1)) * (long)STATE_ELEMS;

                const float *bxp, *bzp, *wy, *by;
                const uint4 *wq5, *wq3;
                if (l == 0) {
                    wq5 = q5a + (long)s * 5 * 25 * 512;  wq3 = q3a + (long)s * 5 * 9 * 512;
                    bxp = b_x0 + s * 128;  bzp = b_z0 + s * 128;
                    wy  = w_y0 + (long)s * 32 * 64;  by = b_y0 + s * 32;
                } else {
                    int qq = (l - 1) * 3 + s;
                    wq5 = q5b + (long)qq * 6 * 25 * 512;  wq3 = q3b + (long)qq * 6 * 9 * 512;
                    bxp = b_x1 + qq * 128;  bzp = b_z1 + qq * 128;
                    wy  = w_y1 + (long)qq * 32 * 64;  by = b_y1 + qq * 32;
                }

                if (l == 0)
                    cell_mma<5><<<256, 256, SMEMSZ>>>(apack, srcx, srcz, wq5, wq3,
                                                      bxp, bzp, dstx, dstz);
                else
                    cell_mma<6><<<256, 256, SMEMSZ>>>(apack, srcx, srcz, wq5, wq3,
                                                      bxp, bzp, dstx, dstz);

                float* ydst = yb + ((l & 1) * 3 + s) * (long)YBUF_ELEMS;

                const bool last_cell = (l == 2 && s == 2);
                if (!last_cell) {
                    int ln = (s < 2) ? l : l + 1;
                    int sn = (s < 2) ? s + 1 : 0;
                    const float* xn; int xbsn;
                    float *sxn, *szn;
                    xinput(step, ln, sn, xn, xbsn);
                    if (sn == 0) statesrc(step, ln, sn, sxn, szn);
                    else { sxn = dstx; szn = dstz; }
                    if (ln == 0)
                        post_kernel<1, 5><<<dim3(16, 4, 9), 256>>>(
                            dstx, dstz, wy, by, ydst, xn, xbsn, sxn, szn, apack);
                    else
                        post_kernel<32, 6><<<dim3(16, 4, 10), 256>>>(
                            dstx, dstz, wy, by, ydst, xn, xbsn, sxn, szn, apack);
                } else {
                    post_kernel<32, 6><<<dim3(16, 4, 4), 256>>>(
                        dstx, dstz, wy, by, ydst, nullptr, 0, dstx, dstz, apack);
                }
            }
        }
    }
    final_kernel<<<64, 256>>>(ylast, w_last, pred + (long)(STEPS - 1) * NB * HW,
                              out + (long)(STEPS - 1 - 8) * HW);
}